// round 11
// baseline (speedup 1.0000x reference)
#include <cuda_runtime.h>
#include <cuda_bf16.h>
#include <math.h>
#include <stdint.h>

// ---------------- problem constants ----------------
#define N_HALF 4096
#define N2     8192
#define Dm     256
#define EPSN   1e-8f
#define NBLK   64            // 8192 / 128 row blocks
#define NTILE  2080          // NBLK*(NBLK+1)/2 upper-tri tiles
#define GRID   148           // persistent CTAs

// ---------------- device scratch ----------------
__device__ __align__(16) __nv_bfloat16 gH[N2 * Dm];   // hi part, row-major
__device__ __align__(16) __nv_bfloat16 gL[N2 * Dm];   // lo part, row-major
// partials: slot o = "other" block; each (o,row) written exactly once
__device__ float g_pf [NBLK][N2];   // partial expsum (fixed shift C = 1/T)
__device__ float g_pmv[NBLK][N2];   // partial max sim
__device__ int   g_pmc[NBLK][N2];   // partial argmax col (global)
__device__ float g_tgt[N2];         // target logit per row
__device__ float g_redl[32];
__device__ int   g_redc[32];

// ---------------- PTX helpers (sm_80-era: compile under compute_103) ------
__device__ __forceinline__ uint32_t smem_u32(const void* p) {
    uint32_t a;
    asm("{ .reg .u64 t; cvta.to.shared.u64 t, %1; cvt.u32.u64 %0, t; }" : "=r"(a) : "l"(p));
    return a;
}
__device__ __forceinline__ void cp16(uint32_t sdst, const void* gsrc) {
    asm volatile("cp.async.cg.shared.global [%0], [%1], 16;" :: "r"(sdst), "l"(gsrc) : "memory");
}
__device__ __forceinline__ void cp_commit() {
    asm volatile("cp.async.commit_group;" ::: "memory");
}
__device__ __forceinline__ void cp_wait2() {
    asm volatile("cp.async.wait_group 2;" ::: "memory");
}
__device__ __forceinline__ void cp_wait0() {
    asm volatile("cp.async.wait_group 0;" ::: "memory");
}
__device__ __forceinline__ void ldm_x4(uint32_t* r, uint32_t addr) {
    asm volatile("ldmatrix.sync.aligned.m8n8.x4.shared.b16 {%0,%1,%2,%3}, [%4];"
        : "=r"(r[0]), "=r"(r[1]), "=r"(r[2]), "=r"(r[3]) : "r"(addr));
}
__device__ __forceinline__ void mma16816(float* d, const uint32_t* a, uint32_t b0, uint32_t b1) {
    asm volatile("mma.sync.aligned.m16n8k16.row.col.f32.bf16.bf16.f32 "
        "{%0,%1,%2,%3}, {%4,%5,%6,%7}, {%8,%9}, {%0,%1,%2,%3};"
        : "+f"(d[0]), "+f"(d[1]), "+f"(d[2]), "+f"(d[3])
        : "r"(a[0]), "r"(a[1]), "r"(a[2]), "r"(a[3]), "r"(b0), "r"(b1));
}

// smem map (offsets from 1024-aligned base)
#define SM_AH   0u          // 128 x 256 bf16 hi = 64KB (512B rows, swizzled)
#define SM_AL   65536u      // lo panel
#define SM_B    131072u     // 4 stages x 16KB (128 rows x 64 bf16, swizzled)
// dedicated epilogue reduction scratch
#define SM_RF   196608u              // float[2][128] row expsum (by wn)
#define SM_RV   (SM_RF + 1024u)
#define SM_RC   (SM_RV + 1024u)
#define SM_CF   (SM_RC + 1024u)     // float[4][128] col expsum (by wm)
#define SM_CV   (SM_CF + 2048u)
#define SM_CC   (SM_CV + 2048u)
#define SMEM_BYTES (196608 + 9216 + 1024)

// ---------------- kernel 1: normalize + bf16 hi/lo split ----------------
__global__ void normalize_kernel(const float* __restrict__ z1,
                                 const float* __restrict__ z2) {
    int row  = blockIdx.x * 8 + (threadIdx.x >> 5);
    int lane = threadIdx.x & 31;
    const float* src = (row < N_HALF) ? (z1 + (size_t)row * Dm)
                                      : (z2 + (size_t)(row - N_HALF) * Dm);
    float4 a = *reinterpret_cast<const float4*>(src + lane * 8);
    float4 b = *reinterpret_cast<const float4*>(src + lane * 8 + 4);
    float s = a.x*a.x + a.y*a.y + a.z*a.z + a.w*a.w
            + b.x*b.x + b.y*b.y + b.z*b.z + b.w*b.w;
    #pragma unroll
    for (int off = 16; off > 0; off >>= 1)
        s += __shfl_xor_sync(0xffffffffu, s, off);
    float sc = 1.0f / fmaxf(sqrtf(s), EPSN);
    float v[8] = {a.x*sc, a.y*sc, a.z*sc, a.w*sc, b.x*sc, b.y*sc, b.z*sc, b.w*sc};
    union { __nv_bfloat16 h[8]; uint4 u; } H, L;
    #pragma unroll
    for (int i = 0; i < 8; i++) {
        H.h[i] = __float2bfloat16(v[i]);
        L.h[i] = __float2bfloat16(v[i] - __bfloat162float(H.h[i]));
    }
    *reinterpret_cast<uint4*>((uint8_t*)gH + (size_t)row * 512 + lane * 16) = H.u;
    *reinterpret_cast<uint4*>((uint8_t*)gL + (size_t)row * 512 + lane * 16) = L.u;
}

// ---------------- kernel 2: persistent symmetric HMMA split-GEMM ----------
// 148 persistent CTAs; bi-major triangular tile ranges, A reloaded on bi change.
// 8 warps (256 thr): wm = wid&3 (32-row strip), wn = wid>>2 (64-col strip).
// B: 4-stage ring of K=64 chunks (8 chunks/tile), ONE sync per chunk.
__global__ void __launch_bounds__(256, 1)
sim_hmma_kernel(const float* __restrict__ lt) {
    extern __shared__ char smraw[];
    uint32_t sb0 = smem_u32(smraw);
    uint32_t sb  = (sb0 + 1023u) & ~1023u;
    char* smb    = smraw + (sb - sb0);

    const int tid  = threadIdx.x;
    const int lane = tid & 31;
    const int wid  = tid >> 5;
    const int wm   = wid & 3;
    const int wn   = wid >> 2;

    const int cta = blockIdx.x;
    const int t0  = (cta * NTILE) / GRID;
    const int t1  = ((cta + 1) * NTILE) / GRID;

    const float invT = expf(-lt[0]);

    // decode starting (bi, bj): f(bi) = bi*(129-bi)/2
    int bi = 0;
    while ((bi + 1) * (128 - bi) / 2 <= t0) bi++;
    int bj = bi + (t0 - bi * (129 - bi) / 2);

    // B load cursor (chunks stream continuously across tiles)
    int ld_bi = bi, ld_bj = bj, ld_q = 0;
    int lcnt = 0, ccnt = 0;
    const int totalc = (t1 - t0) * 8;
    int bi_loaded = -1;
    bool fullw = true;

    const uint32_t a_lo = (lane & 15) * 512u + (lane >> 4) * 16u;
    const uint32_t b_lo = (lane & 15) * 128u + (lane >> 4) * 16u;
    const uint32_t lxr  = (uint32_t)(lane & 7) << 4;
    const uint32_t AhB  = sb + SM_AH + wm * 16384u;
    const uint32_t AlB  = sb + SM_AL + wm * 16384u;

    auto issueB = [&]() {
        const uint8_t* g = (ld_q & 1) ? (const uint8_t*)gL : (const uint8_t*)gH;
        const int kb2 = (ld_q >> 1) * 128;          // byte offset within 512B row
        const uint32_t st = (uint32_t)(lcnt & 3);
        int u = tid;
        #pragma unroll
        for (int i = 0; i < 4; i++, u += 256) {
            int rr = u >> 3, ku = u & 7;
            const uint8_t* gsrc = g + ((size_t)(ld_bj * 128 + rr)) * 512 + kb2 + ku * 16;
            uint32_t sdst = (sb + SM_B + st * 16384u + (uint32_t)(rr * 128 + ku * 16))
                            ^ (uint32_t)((rr & 7) << 4);
            cp16(sdst, gsrc);
        }
        cp_commit();
        lcnt++;
        if (++ld_q == 8) {
            ld_q = 0;
            if (++ld_bj == NBLK) { ld_bi++; ld_bj = ld_bi; }
        }
    };

    auto loadA = [&](int bib) {
        int u = tid;
        #pragma unroll
        for (int i = 0; i < 32; i++, u += 256) {
            int panel = u >> 12, rr = (u >> 5) & 127, ku = u & 31;
            const uint8_t* g = panel ? (const uint8_t*)gL : (const uint8_t*)gH;
            const uint8_t* gsrc = g + ((size_t)(bib * 128 + rr)) * 512 + ku * 16;
            uint32_t sdst = (sb + panel * 65536u + (uint32_t)(rr * 512 + ku * 16))
                            ^ (uint32_t)((rr & 7) << 4);
            cp16(sdst, gsrc);
        }
        cp_commit();
    };

    for (int t = t0; t < t1; t++) {
        if (bi != bi_loaded) {
            loadA(bi);                 // A group inserted -> full drain at next wait
            bi_loaded = bi;
            fullw = true;
        }
        while (lcnt < ccnt + 3 && lcnt < totalc) issueB();

        float acc[2][8][4];
        #pragma unroll
        for (int mf = 0; mf < 2; mf++)
            #pragma unroll
            for (int nf = 0; nf < 8; nf++)
                #pragma unroll
                for (int v = 0; v < 4; v++) acc[mf][nf][v] = 0.0f;

        #pragma unroll
        for (int q = 0; q < 8; q++) {
            if (fullw) { cp_wait0(); fullw = false; } else { cp_wait2(); }
            __syncthreads();
            // stage (ccnt-1)&3 is now provably free -> issue chunk ccnt+3 into it
            if (lcnt < totalc) issueB();

            const uint32_t st = (uint32_t)(ccnt & 3);
            const int kb = (q >> 1) * 64;
            const bool dual = ((q & 1) == 0);   // Bh chunk -> hh + lh terms
            const uint32_t Bst = sb + SM_B + st * 16384u + wn * 8192u;

            #pragma unroll
            for (int kk = 0; kk < 64; kk += 16) {
                uint32_t bfr[4][4];
                #pragma unroll
                for (int nb = 0; nb < 4; nb++)
                    ldm_x4(bfr[nb], (Bst + nb * 2048u + kk * 2u + b_lo) ^ lxr);
                uint32_t af[2][4];
                ldm_x4(af[0], (AhB + 0u    + (kb + kk) * 2u + a_lo) ^ lxr);
                ldm_x4(af[1], (AhB + 8192u + (kb + kk) * 2u + a_lo) ^ lxr);
                #pragma unroll
                for (int mf = 0; mf < 2; mf++)
                    #pragma unroll
                    for (int nb = 0; nb < 4; nb++) {
                        mma16816(acc[mf][nb*2  ], af[mf], bfr[nb][0], bfr[nb][2]);
                        mma16816(acc[mf][nb*2+1], af[mf], bfr[nb][1], bfr[nb][3]);
                    }
                if (dual) {
                    uint32_t al[2][4];
                    ldm_x4(al[0], (AlB + 0u    + (kb + kk) * 2u + a_lo) ^ lxr);
                    ldm_x4(al[1], (AlB + 8192u + (kb + kk) * 2u + a_lo) ^ lxr);
                    #pragma unroll
                    for (int mf = 0; mf < 2; mf++)
                        #pragma unroll
                        for (int nb = 0; nb < 4; nb++) {
                            mma16816(acc[mf][nb*2  ], al[mf], bfr[nb][0], bfr[nb][2]);
                            mma16816(acc[mf][nb*2+1], al[mf], bfr[nb][1], bfr[nb][3]);
                        }
                }
            }
            ccnt++;
        }

        // ============== epilogue: dual-direction reduction ==============
        const int  lq     = lane >> 2;
        const bool isDiag = (bi == bj);
        const bool isTgt  = (bj == bi + 32);

        float fsum[4], mv[4];   int mc[4];    // row direction (4 row slots)
        float csum[16], cv[16]; int cim[16];  // col direction (16 col slots)
        #pragma unroll
        for (int s = 0; s < 4; s++)  { fsum[s] = 0.0f; mv[s] = -INFINITY; mc[s] = 0; }
        #pragma unroll
        for (int c = 0; c < 16; c++) { csum[c] = 0.0f; cv[c] = -INFINITY; cim[c] = 0; }

        #pragma unroll
        for (int mf = 0; mf < 2; mf++)
            #pragma unroll
            for (int nf = 0; nf < 8; nf++)
                #pragma unroll
                for (int v = 0; v < 4; v++) {
                    const int rl = wm * 32 + mf * 16 + lq + (v >> 1) * 8;
                    const int cl = wn * 64 + nf * 8 + (lane & 3) * 2 + (v & 1);
                    const float sv = acc[mf][nf][v];
                    const float e  = __expf((sv - 1.0f) * invT);
                    const bool same = (rl == cl);
                    if (isTgt && same) {
                        const float tv = sv * invT;
                        g_tgt[bi * 128 + rl]        = tv;
                        g_tgt[bi * 128 + rl + 4096] = tv;
                    }
                    if (!(isDiag && same)) {
                        const int s = mf * 2 + (v >> 1);
                        const int c = nf * 2 + (v & 1);
                        fsum[s] += e;
                        if (sv > mv[s]) { mv[s] = sv; mc[s] = cl; }
                        csum[c] += e;
                        if (sv > cv[c]) { cv[c] = sv; cim[c] = rl; }
                    }
                }

        // row dir: quad shfl reduce (over lane&3)
        #pragma unroll
        for (int s = 0; s < 4; s++) {
            #pragma unroll
            for (int o = 1; o < 4; o <<= 1) {
                float of = __shfl_xor_sync(0xffffffffu, fsum[s], o);
                float ov = __shfl_xor_sync(0xffffffffu, mv[s],   o);
                int   oc = __shfl_xor_sync(0xffffffffu, mc[s],   o);
                fsum[s] += of;
                if (ov > mv[s] || (ov == mv[s] && oc < mc[s])) { mv[s] = ov; mc[s] = oc; }
            }
        }
        if ((lane & 3) == 0) {
            #pragma unroll
            for (int s = 0; s < 4; s++) {
                const int rl = wm * 32 + s * 8 + lq;
                *(float*)(smb + SM_RF + (wn * 128 + rl) * 4) = fsum[s];
                *(float*)(smb + SM_RV + (wn * 128 + rl) * 4) = mv[s];
                *(int*)  (smb + SM_RC + (wn * 128 + rl) * 4) = mc[s];
            }
        }
        // col dir: shfl reduce over lq (xor 4,8,16)
        #pragma unroll
        for (int c = 0; c < 16; c++) {
            #pragma unroll
            for (int o = 4; o < 32; o <<= 1) {
                float of = __shfl_xor_sync(0xffffffffu, csum[c], o);
                float ov = __shfl_xor_sync(0xffffffffu, cv[c],   o);
                int   oi = __shfl_xor_sync(0xffffffffu, cim[c],  o);
                csum[c] += of;
                if (ov > cv[c] || (ov == cv[c] && oi < cim[c])) { cv[c] = ov; cim[c] = oi; }
            }
        }
        if (lane < 4) {
            #pragma unroll
            for (int c = 0; c < 16; c++) {
                const int cl = wn * 64 + (c >> 1) * 8 + lane * 2 + (c & 1);
                *(float*)(smb + SM_CF + (wm * 128 + cl) * 4) = csum[c];
                *(float*)(smb + SM_CV + (wm * 128 + cl) * 4) = cv[c];
                *(int*)  (smb + SM_CC + (wm * 128 + cl) * 4) = cim[c];
            }
        }
        __syncthreads();

        if (tid < 128) {
            {   // row direction -> rows of block bi, slot bj
                const int rl = tid;
                float f = 0.0f, bv = -INFINITY; int bc = 0;
                #pragma unroll
                for (int w = 0; w < 2; w++) {
                    f += *(float*)(smb + SM_RF + (w * 128 + rl) * 4);
                    float v2 = *(float*)(smb + SM_RV + (w * 128 + rl) * 4);
                    int   c2 = *(int*)  (smb + SM_RC + (w * 128 + rl) * 4);
                    if (v2 > bv) { bv = v2; bc = c2; }
                }
                const int row = bi * 128 + rl;
                g_pf [bj][row] = f;
                g_pmv[bj][row] = bv;
                g_pmc[bj][row] = bj * 128 + bc;
            }
            if (!isDiag) {   // col direction -> rows of block bj, slot bi
                const int cl = tid;
                float f = 0.0f, bv = -INFINITY; int br = 0;
                #pragma unroll
                for (int w = 0; w < 4; w++) {
                    f += *(float*)(smb + SM_CF + (w * 128 + cl) * 4);
                    float v2 = *(float*)(smb + SM_CV + (w * 128 + cl) * 4);
                    int   r2 = *(int*)  (smb + SM_CC + (w * 128 + cl) * 4);
                    if (v2 > bv) { bv = v2; br = r2; }
                }
                const int row = bj * 128 + cl;
                g_pf [bi][row] = f;
                g_pmv[bi][row] = bv;
                g_pmc[bi][row] = bi * 128 + br;
            }
        }

        if (++bj == NBLK) { bi++; bj = bi; }
    }
}

// ---------------- kernel 3a: per-row reduce over 64 slots ----------------
__global__ void finalizeA_kernel(const float* __restrict__ lt) {
    __shared__ float sl[256];
    __shared__ int   sc[256];
    const int tid = threadIdx.x;
    const int row = blockIdx.x * 256 + tid;
    const float invT = expf(-lt[0]);
    float fs = 0.0f, bv = -INFINITY;
    int bc = -1;
    #pragma unroll 8
    for (int o = 0; o < NBLK; o++) {
        fs += g_pf[o][row];
        float v = g_pmv[o][row];
        int   c = g_pmc[o][row];
        if (v > bv || (v == bv && c < bc)) { bv = v; bc = c; }
    }
    float lse = invT + logf(fs);
    sl[tid] = lse - g_tgt[row];
    sc[tid] = (bc == (row ^ 4096)) ? 1 : 0;
    __syncthreads();
    for (int s = 128; s > 0; s >>= 1) {
        if (tid < s) { sl[tid] += sl[tid + s]; sc[tid] += sc[tid + s]; }
        __syncthreads();
    }
    if (tid == 0) { g_redl[blockIdx.x] = sl[0]; g_redc[blockIdx.x] = sc[0]; }
}

// ---------------- kernel 3b: final scalar ----------------
__global__ void finalizeB_kernel(float* __restrict__ out) {
    const int tid = threadIdx.x;  // 32 threads
    float l = g_redl[tid];
    int   c = g_redc[tid];
    #pragma unroll
    for (int o = 16; o > 0; o >>= 1) {
        l += __shfl_xor_sync(0xffffffffu, l, o);
        c += __shfl_xor_sync(0xffffffffu, c, o);
    }
    if (tid == 0) {
        out[0] = l / (float)N2;
        out[1] = 0.5f * (float)c;
    }
}

extern "C" void kernel_launch(void* const* d_in, const int* in_sizes, int n_in,
                              void* d_out, int out_size) {
    const float* z1 = (const float*)d_in[0];
    const float* z2 = (const float*)d_in[1];
    const float* lt = (const float*)d_in[2];
    float* out = (float*)d_out;

    cudaFuncSetAttribute(sim_hmma_kernel,
                         cudaFuncAttributeMaxDynamicSharedMemorySize, SMEM_BYTES);

    normalize_kernel<<<N2 / 8, 256>>>(z1, z2);
    sim_hmma_kernel<<<GRID, 256, SMEM_BYTES>>>(lt);
    finalizeA_kernel<<<32, 256>>>(lt);
    finalizeB_kernel<<<1, 32>>>(out);
}

// round 12
// speedup vs baseline: 1.8687x; 1.8687x over previous
#include <cuda_runtime.h>
#include <cuda_fp16.h>
#include <math.h>
#include <stdint.h>

// ---------------- problem constants ----------------
#define N_HALF 4096
#define N2     8192
#define Dm     256
#define EPSN   1e-8f
#define NBLK   64            // 8192 / 128 row blocks
#define NTILE  2080          // NBLK*(NBLK+1)/2 upper-tri tiles
#define GRID   148           // persistent CTAs

// ---------------- device scratch ----------------
__device__ __align__(16) __half gF[N2 * Dm];   // fp16 normalized rows (4MB, L2-resident)
// partials: slot o = "other" block; each (o,row) written exactly once
__device__ float g_pf [NBLK][N2];   // partial expsum (fixed shift C = 1/T)
__device__ float g_pmv[NBLK][N2];   // partial max sim
__device__ int   g_pmc[NBLK][N2];   // partial argmax col (global)
__device__ float g_tgt[N2];         // target logit per row
__device__ float g_redl[32];
__device__ int   g_redc[32];

// ---------------- PTX helpers (sm_80-era: compile under compute_103) ------
__device__ __forceinline__ uint32_t smem_u32(const void* p) {
    uint32_t a;
    asm("{ .reg .u64 t; cvta.to.shared.u64 t, %1; cvt.u32.u64 %0, t; }" : "=r"(a) : "l"(p));
    return a;
}
__device__ __forceinline__ void cp16(uint32_t sdst, const void* gsrc) {
    asm volatile("cp.async.cg.shared.global [%0], [%1], 16;" :: "r"(sdst), "l"(gsrc) : "memory");
}
__device__ __forceinline__ void cp_commit() {
    asm volatile("cp.async.commit_group;" ::: "memory");
}
__device__ __forceinline__ void cp_wait0() {
    asm volatile("cp.async.wait_group 0;" ::: "memory");
}
__device__ __forceinline__ void ldm_x4(uint32_t* r, uint32_t addr) {
    asm volatile("ldmatrix.sync.aligned.m8n8.x4.shared.b16 {%0,%1,%2,%3}, [%4];"
        : "=r"(r[0]), "=r"(r[1]), "=r"(r[2]), "=r"(r[3]) : "r"(addr));
}
__device__ __forceinline__ void mma16816(float* d, const uint32_t* a, uint32_t b0, uint32_t b1) {
    asm volatile("mma.sync.aligned.m16n8k16.row.col.f32.f16.f16.f32 "
        "{%0,%1,%2,%3}, {%4,%5,%6,%7}, {%8,%9}, {%0,%1,%2,%3};"
        : "+f"(d[0]), "+f"(d[1]), "+f"(d[2]), "+f"(d[3])
        : "r"(a[0]), "r"(a[1]), "r"(a[2]), "r"(a[3]), "r"(b0), "r"(b1));
}

// smem map (offsets from 1024-aligned base)
#define SM_A    0u           // 128 x 256 fp16 = 64KB (512B rows, swizzled)
#define SM_B    65536u       // 2 x 64KB full B tiles (double buffer)
// dedicated epilogue reduction scratch
#define SM_RF   196608u              // float[4][128] row expsum (by wn)
#define SM_RV   (SM_RF + 2048u)
#define SM_RC   (SM_RV + 2048u)
#define SM_CF   (SM_RC + 2048u)      // float[4][128] col expsum (by wm)
#define SM_CV   (SM_CF + 2048u)
#define SM_CC   (SM_CV + 2048u)
#define SMEM_BYTES (196608 + 12288 + 1024)

// ---------------- kernel 1: normalize + fp16 convert ----------------
__global__ void normalize_kernel(const float* __restrict__ z1,
                                 const float* __restrict__ z2) {
    int row  = blockIdx.x * 8 + (threadIdx.x >> 5);
    int lane = threadIdx.x & 31;
    const float* src = (row < N_HALF) ? (z1 + (size_t)row * Dm)
                                      : (z2 + (size_t)(row - N_HALF) * Dm);
    float4 a = *reinterpret_cast<const float4*>(src + lane * 8);
    float4 b = *reinterpret_cast<const float4*>(src + lane * 8 + 4);
    float s = a.x*a.x + a.y*a.y + a.z*a.z + a.w*a.w
            + b.x*b.x + b.y*b.y + b.z*b.z + b.w*b.w;
    #pragma unroll
    for (int off = 16; off > 0; off >>= 1)
        s += __shfl_xor_sync(0xffffffffu, s, off);
    float sc = 1.0f / fmaxf(sqrtf(s), EPSN);
    float v[8] = {a.x*sc, a.y*sc, a.z*sc, a.w*sc, b.x*sc, b.y*sc, b.z*sc, b.w*sc};
    union { __half h[8]; uint4 u; } H;
    #pragma unroll
    for (int i = 0; i < 8; i++) H.h[i] = __float2half_rn(v[i]);
    *reinterpret_cast<uint4*>((uint8_t*)gF + (size_t)row * 512 + lane * 16) = H.u;
}

// ---------------- kernel 2: persistent symmetric fp16 HMMA GEMM ----------
// 148 persistent CTAs; bi-major triangular tile ranges; A panel reloaded on
// bi change. 16 warps (512 thr): wm = wid&3 (32-row), wn = wid>>2 (32-col).
// Full 64KB B tile double-buffered; ONE __syncthreads per tile.
__global__ void __launch_bounds__(512, 1)
sim_hmma_kernel(const float* __restrict__ lt) {
    extern __shared__ char smraw[];
    uint32_t sb0 = smem_u32(smraw);
    uint32_t sb  = (sb0 + 1023u) & ~1023u;
    char* smb    = smraw + (sb - sb0);

    const int tid  = threadIdx.x;
    const int lane = tid & 31;
    const int wid  = tid >> 5;
    const int wm   = wid & 3;
    const int wn   = wid >> 2;

    const int cta = blockIdx.x;
    const int t0  = (cta * NTILE) / GRID;
    const int t1  = ((cta + 1) * NTILE) / GRID;

    const float invT = expf(-lt[0]);

    // decode starting (bi, bj): f(bi) = bi*(129-bi)/2
    int bi = 0;
    while ((bi + 1) * (128 - bi) / 2 <= t0) bi++;
    int bj = bi + (t0 - bi * (129 - bi) / 2);

    const uint32_t a_lo = (lane & 15) * 512u + (lane >> 4) * 16u;
    const uint32_t lxr  = (uint32_t)(lane & 7) << 4;
    const uint32_t Ab   = sb + SM_A + wm * 16384u;     // wm*32 rows * 512B

    auto loadA = [&](int bib) {
        int u = tid;
        #pragma unroll
        for (int i = 0; i < 8; i++, u += 512) {
            int rr = u >> 5, ku = u & 31;
            const uint8_t* gsrc = (const uint8_t*)gF + ((size_t)(bib * 128 + rr)) * 512 + ku * 16;
            uint32_t sdst = (sb + SM_A + (uint32_t)(rr * 512 + ku * 16))
                            ^ (uint32_t)((rr & 7) << 4);
            cp16(sdst, gsrc);
        }
        cp_commit();
    };
    auto loadB = [&](int bjb, int buf) {
        int u = tid;
        #pragma unroll
        for (int i = 0; i < 8; i++, u += 512) {
            int rr = u >> 5, ku = u & 31;
            const uint8_t* gsrc = (const uint8_t*)gF + ((size_t)(bjb * 128 + rr)) * 512 + ku * 16;
            uint32_t sdst = (sb + SM_B + (uint32_t)buf * 65536u + (uint32_t)(rr * 512 + ku * 16))
                            ^ (uint32_t)((rr & 7) << 4);
            cp16(sdst, gsrc);
        }
        cp_commit();
    };

    int loaded_bi = -1;
    bool pending = true;       // loads for tile t must be issued at loop top

    for (int t = t0; t < t1; t++) {
        if (pending) {         // first tile, or A-panel change (serial stall)
            if (bi != loaded_bi) { loadA(bi); loaded_bi = bi; }
            loadB(bj, t & 1);
            pending = false;
        }
        cp_wait0();
        __syncthreads();

        // prefetch next tile's B under current compute (same A panel only)
        int nbi = bi, nbj = bj + 1;
        if (nbj == NBLK) { nbi++; nbj = nbi; }
        if (t + 1 < t1) {
            if (nbi == loaded_bi) loadB(nbj, (t + 1) & 1);
            else pending = true;
        }

        // ---- compute 128x128 tile over full K=256 ----
        float acc[2][4][4];
        #pragma unroll
        for (int mf = 0; mf < 2; mf++)
            #pragma unroll
            for (int nb = 0; nb < 4; nb++)
                #pragma unroll
                for (int v = 0; v < 4; v++) acc[mf][nb][v] = 0.0f;

        const uint32_t Bb = sb + SM_B + (uint32_t)(t & 1) * 65536u + wn * 16384u;
        #pragma unroll
        for (int kk = 0; kk < 256; kk += 16) {
            uint32_t bfr[2][4], af[2][4];
            ldm_x4(bfr[0], (Bb + 0u    + kk * 2u + a_lo) ^ lxr);
            ldm_x4(bfr[1], (Bb + 8192u + kk * 2u + a_lo) ^ lxr);
            ldm_x4(af[0],  (Ab + 0u    + kk * 2u + a_lo) ^ lxr);
            ldm_x4(af[1],  (Ab + 8192u + kk * 2u + a_lo) ^ lxr);
            #pragma unroll
            for (int mf = 0; mf < 2; mf++)
                #pragma unroll
                for (int g = 0; g < 2; g++) {
                    mma16816(acc[mf][g*2  ], af[mf], bfr[g][0], bfr[g][2]);
                    mma16816(acc[mf][g*2+1], af[mf], bfr[g][1], bfr[g][3]);
                }
        }

        // ============== epilogue: dual-direction reduction ==============
        const int  lq     = lane >> 2;
        const bool isDiag = (bi == bj);
        const bool isTgt  = (bj == bi + 32);

        float fsum[4], mv[4]; int mc[4];     // row direction (4 row slots)
        float csum[8], cv[8]; int cim[8];    // col direction (8 col slots)
        #pragma unroll
        for (int s = 0; s < 4; s++) { fsum[s] = 0.0f; mv[s] = -INFINITY; mc[s] = 0; }
        #pragma unroll
        for (int c = 0; c < 8; c++) { csum[c] = 0.0f; cv[c] = -INFINITY; cim[c] = 0; }

        #pragma unroll
        for (int mf = 0; mf < 2; mf++)
            #pragma unroll
            for (int nb = 0; nb < 4; nb++)
                #pragma unroll
                for (int v = 0; v < 4; v++) {
                    const int rl = wm * 32 + mf * 16 + lq + (v >> 1) * 8;
                    const int cl = wn * 32 + nb * 8 + (lane & 3) * 2 + (v & 1);
                    const float sv = acc[mf][nb][v];
                    const float e  = __expf((sv - 1.0f) * invT);
                    const bool same = (rl == cl);
                    if (isTgt && same) {
                        const float tv = sv * invT;
                        g_tgt[bi * 128 + rl]        = tv;
                        g_tgt[bi * 128 + rl + 4096] = tv;
                    }
                    if (!(isDiag && same)) {
                        const int s = mf * 2 + (v >> 1);
                        const int c = nb * 2 + (v & 1);
                        fsum[s] += e;
                        if (sv > mv[s]) { mv[s] = sv; mc[s] = cl; }
                        csum[c] += e;
                        if (sv > cv[c]) { cv[c] = sv; cim[c] = rl; }
                    }
                }

        // row dir: quad shfl reduce (over lane&3)
        #pragma unroll
        for (int s = 0; s < 4; s++) {
            #pragma unroll
            for (int o = 1; o < 4; o <<= 1) {
                float of = __shfl_xor_sync(0xffffffffu, fsum[s], o);
                float ov = __shfl_xor_sync(0xffffffffu, mv[s],   o);
                int   oc = __shfl_xor_sync(0xffffffffu, mc[s],   o);
                fsum[s] += of;
                if (ov > mv[s] || (ov == mv[s] && oc < mc[s])) { mv[s] = ov; mc[s] = oc; }
            }
        }
        if ((lane & 3) == 0) {
            #pragma unroll
            for (int s = 0; s < 4; s++) {
                const int rl = wm * 32 + s * 8 + lq;
                *(float*)(smb + SM_RF + (wn * 128 + rl) * 4) = fsum[s];
                *(float*)(smb + SM_RV + (wn * 128 + rl) * 4) = mv[s];
                *(int*)  (smb + SM_RC + (wn * 128 + rl) * 4) = mc[s];
            }
        }
        // col dir: shfl reduce over lq (xor 4,8,16)
        #pragma unroll
        for (int c = 0; c < 8; c++) {
            #pragma unroll
            for (int o = 4; o < 32; o <<= 1) {
                float of = __shfl_xor_sync(0xffffffffu, csum[c], o);
                float ov = __shfl_xor_sync(0xffffffffu, cv[c],   o);
                int   oi = __shfl_xor_sync(0xffffffffu, cim[c],  o);
                csum[c] += of;
                if (ov > cv[c] || (ov == cv[c] && oi < cim[c])) { cv[c] = ov; cim[c] = oi; }
            }
        }
        if (lane < 4) {
            #pragma unroll
            for (int c = 0; c < 8; c++) {
                const int cl = wn * 32 + (c >> 1) * 8 + lane * 2 + (c & 1);
                *(float*)(smb + SM_CF + (wm * 128 + cl) * 4) = csum[c];
                *(float*)(smb + SM_CV + (wm * 128 + cl) * 4) = cv[c];
                *(int*)  (smb + SM_CC + (wm * 128 + cl) * 4) = cim[c];
            }
        }
        __syncthreads();

        if (tid < 128) {
            {   // row direction -> rows of block bi, slot bj
                const int rl = tid;
                float f = 0.0f, bv = -INFINITY; int bc = 0;
                #pragma unroll
                for (int w = 0; w < 4; w++) {
                    f += *(float*)(smb + SM_RF + (w * 128 + rl) * 4);
                    float v2 = *(float*)(smb + SM_RV + (w * 128 + rl) * 4);
                    int   c2 = *(int*)  (smb + SM_RC + (w * 128 + rl) * 4);
                    if (v2 > bv) { bv = v2; bc = c2; }
                }
                const int row = bi * 128 + rl;
                g_pf [bj][row] = f;
                g_pmv[bj][row] = bv;
                g_pmc[bj][row] = bj * 128 + bc;
            }
            if (!isDiag) {   // col direction -> rows of block bj, slot bi
                const int cl = tid;
                float f = 0.0f, bv = -INFINITY; int br = 0;
                #pragma unroll
                for (int w = 0; w < 4; w++) {
                    f += *(float*)(smb + SM_CF + (w * 128 + cl) * 4);
                    float v2 = *(float*)(smb + SM_CV + (w * 128 + cl) * 4);
                    int   r2 = *(int*)  (smb + SM_CC + (w * 128 + cl) * 4);
                    if (v2 > bv) { bv = v2; br = r2; }
                }
                const int row = bj * 128 + cl;
                g_pf [bi][row] = f;
                g_pmv[bi][row] = bv;
                g_pmc[bi][row] = bi * 128 + br;
            }
        }

        bi = nbi; bj = nbj;
    }
}

// ---------------- kernel 3a: per-row reduce over 64 slots ----------------
__global__ void finalizeA_kernel(const float* __restrict__ lt) {
    __shared__ float sl[256];
    __shared__ int   sc[256];
    const int tid = threadIdx.x;
    const int row = blockIdx.x * 256 + tid;
    const float invT = expf(-lt[0]);
    float fs = 0.0f, bv = -INFINITY;
    int bc = -1;
    #pragma unroll 8
    for (int o = 0; o < NBLK; o++) {
        fs += g_pf[o][row];
        float v = g_pmv[o][row];
        int   c = g_pmc[o][row];
        if (v > bv || (v == bv && c < bc)) { bv = v; bc = c; }
    }
    float lse = invT + logf(fs);
    sl[tid] = lse - g_tgt[row];
    sc[tid] = (bc == (row ^ 4096)) ? 1 : 0;
    __syncthreads();
    for (int s = 128; s > 0; s >>= 1) {
        if (tid < s) { sl[tid] += sl[tid + s]; sc[tid] += sc[tid + s]; }
        __syncthreads();
    }
    if (tid == 0) { g_redl[blockIdx.x] = sl[0]; g_redc[blockIdx.x] = sc[0]; }
}

// ---------------- kernel 3b: final scalar ----------------
__global__ void finalizeB_kernel(float* __restrict__ out) {
    const int tid = threadIdx.x;  // 32 threads
    float l = g_redl[tid];
    int   c = g_redc[tid];
    #pragma unroll
    for (int o = 16; o > 0; o >>= 1) {
        l += __shfl_xor_sync(0xffffffffu, l, o);
        c += __shfl_xor_sync(0xffffffffu, c, o);
    }
    if (tid == 0) {
        out[0] = l / (float)N2;
        out[1] = 0.5f * (float)c;
    }
}

extern "C" void kernel_launch(void* const* d_in, const int* in_sizes, int n_in,
                              void* d_out, int out_size) {
    const float* z1 = (const float*)d_in[0];
    const float* z2 = (const float*)d_in[1];
    const float* lt = (const float*)d_in[2];
    float* out = (float*)d_out;

    cudaFuncSetAttribute(sim_hmma_kernel,
                         cudaFuncAttributeMaxDynamicSharedMemorySize, SMEM_BYTES);

    normalize_kernel<<<N2 / 8, 256>>>(z1, z2);
    sim_hmma_kernel<<<GRID, 512, SMEM_BYTES>>>(lt);
    finalizeA_kernel<<<32, 256>>>(lt);
    finalizeB_kernel<<<1, 32>>>(out);
}